// round 6
// baseline (speedup 1.0000x reference)
#include <cuda_runtime.h>
#include <math.h>
#include <stdint.h>

#define B_   32
#define S_   64
#define T_   48
#define TD   47
#define V_   32000
#define E_   512
#define H_   1024
#define H3_  3072
#define NBLK 64
#define WPBLK (3*128*32*4)       // floats per nb-block of a packed matrix
#define WPSZ  (64*WPBLK)         // floats per packed matrix

// ---------------- device scratch ----------------
__device__ float g_emb  [B_*S_*E_];
__device__ float g_demb [TD*B_*E_];
__device__ float g_gi0  [B_*S_*H3_];
__device__ float g_giemb[TD*B_*H3_];
__device__ float g_enc  [B_*S_*H_];
__device__ float g_proj [B_*S_*H_];
__device__ float g_h0P  [2][B_*H_];      // fragment-packed tf32 state
__device__ float g_h1P  [2][B_*H_];
__device__ float g_h0n  [2][B_*H_];      // full-precision state
__device__ float g_h1n  [2][B_*H_];
__device__ float g_xP   [B_*H_];         // packed ctx
__device__ float g_score[B_*S_];
__device__ float g_cat  [TD*B_*2*H_];
__device__ float g_owr  [V_*2*H_];       // tf32-rounded out_w
__device__ float g_wih0er[H3_*E_];       // rounded enc_wih0
__device__ float g_wih0dr[H3_*(E_+H_)];  // rounded dec_wih0
__device__ float g_wp[7][WPSZ];  // 0:e_hh0 1:e_ih1 2:e_hh1 3:d_hh0 4:d_ih0c 5:d_ih1 6:d_hh1
__device__ unsigned g_count;

__global__ void k_reset() { g_count = 0u; }

__device__ __forceinline__ uint32_t f2tf32(float f) {
    uint32_t u; asm("cvt.rna.tf32.f32 %0, %1;" : "=r"(u) : "f"(f)); return u;
}
__device__ __forceinline__ float roundtf(float f) { return __uint_as_float(f2tf32(f)); }
__device__ __forceinline__ void mma_tf32(float c[4], const uint32_t a[4], const uint32_t b[2]) {
    asm volatile(
        "mma.sync.aligned.m16n8k8.row.col.f32.tf32.tf32.f32 "
        "{%0,%1,%2,%3}, {%4,%5,%6,%7}, {%8,%9}, {%0,%1,%2,%3};\n"
        : "+f"(c[0]), "+f"(c[1]), "+f"(c[2]), "+f"(c[3])
        : "r"(a[0]), "r"(a[1]), "r"(a[2]), "r"(a[3]), "r"(b[0]), "r"(b[1]));
}
// packed-state index for hidden k, batch b (matches m16n8k8 B-fragment order)
__device__ __forceinline__ int pidx(int k, int b) {
    int lane = ((b & 7) << 2) | (k & 3);
    int s = ((b >> 3) << 1) | ((k >> 2) & 1);
    return ((k >> 3) * 32 + lane) * 8 + s;
}

// ---------------- prep kernels ----------------
__global__ void k_round(const float* __restrict__ src, float* __restrict__ dst, int n)
{
    int i = blockIdx.x * 256 + threadIdx.x;
    if (i < n) dst[i] = roundtf(src[i]);
}
// pack W rows [gate*H + nb*16 + j], cols koff..koff+1023 into A-fragment order
__global__ void k_wpack(const float* __restrict__ W, int ldw, int koff, float* __restrict__ WP)
{
    int idx = blockIdx.x * 256 + threadIdx.x;
    if (idx >= WPSZ) return;
    int q    = idx & 3;
    int lane = (idx >> 2) & 31;
    int k8   = (idx >> 7) & 127;
    int rem  = idx >> 14;
    int gate = rem % 3;
    int nb   = rem / 3;
    int g = lane >> 2, tg = lane & 3;
    int j = ((q & 1) << 3) + g;
    int k = k8 * 8 + ((q >> 1) << 2) + tg;
    WP[idx] = roundtf(W[(size_t)(gate * H_ + nb * 16 + j) * ldw + koff + k]);
}
__global__ void k_init(const int* __restrict__ src_ids, const float* __restrict__ enc_emb)
{
    int idx = blockIdx.x * blockDim.x + threadIdx.x;
    if (idx < B_*S_*E_) {
        int m = idx >> 9, k = idx & 511;
        g_emb[idx] = roundtf(enc_emb[(size_t)src_ids[m] * E_ + k]);
    }
}
__global__ void k_demb(const int* __restrict__ tgt_ids, const float* __restrict__ dec_emb)
{
    int idx = blockIdx.x * blockDim.x + threadIdx.x;
    if (idx >= TD*B_*E_) return;
    int m = idx >> 9, k = idx & 511;
    int b = m & 31, t = m >> 5;
    g_demb[idx] = roundtf(dec_emb[(size_t)tgt_ids[b*T_ + t] * E_ + k]);
}

// ---------------- grid barrier ----------------
__device__ __forceinline__ void gbar(unsigned &target) {
    __threadfence();
    __syncthreads();
    if (threadIdx.x == 0) {
        atomicAdd(&g_count, 1u);
        target += NBLK;
        while (*(volatile unsigned*)&g_count < target) { }
    }
    __syncthreads();
}

// ---------------- packed GEMV pass: acc[gate][nt] += WP(nb) @ packed-state ----------------
__device__ __forceinline__ void gemvp(float acc[3][4][4],
        const float* __restrict__ SP, const float* __restrict__ WPm,
        int lane, int warp)
{
    const uint4* sp = (const uint4*)SP;
    const uint4* wp = (const uint4*)WPm;
    int k8beg = warp * 16;
#pragma unroll 4
    for (int k8 = k8beg; k8 < k8beg + 16; k8++) {
        uint4 b01 = __ldcg(sp + (k8 * 32 + lane) * 2);
        uint4 b23 = __ldcg(sp + (k8 * 32 + lane) * 2 + 1);
        uint32_t bf[4][2] = {{b01.x, b01.y}, {b01.z, b01.w},
                             {b23.x, b23.y}, {b23.z, b23.w}};
#pragma unroll
        for (int gate = 0; gate < 3; gate++) {
            uint4 av = __ldg(wp + (gate * 128 + k8) * 32 + lane);
            uint32_t af[4] = {av.x, av.y, av.z, av.w};
#pragma unroll
            for (int nt = 0; nt < 4; nt++) mma_tf32(acc[gate][nt], af, bf[nt]);
        }
    }
}

// reduce 8 warps' frags -> s_out[gate*512 + b*16 + j]; two rounds keep smem < 48KB
__device__ __forceinline__ void reduce3(const float acc[3][4][4],
        float* s_red, float* s_out)
{
    int lane = threadIdx.x & 31, warp = threadIdx.x >> 5;
    int g = lane >> 2, tg = lane & 3;
    float* base = s_red + (warp & 3) * 1632;
    if (warp < 4) {
#pragma unroll
        for (int gate = 0; gate < 3; gate++)
#pragma unroll
        for (int nt = 0; nt < 4; nt++)
#pragma unroll
        for (int q = 0; q < 4; q++) {
            int e = gate*512 + (nt*8 + 2*tg + (q&1))*16 + g + ((q>>1)<<3);
            base[(e>>4)*17 + (e&15)] = acc[gate][nt][q];
        }
    }
    __syncthreads();
    if (warp >= 4) {
#pragma unroll
        for (int gate = 0; gate < 3; gate++)
#pragma unroll
        for (int nt = 0; nt < 4; nt++)
#pragma unroll
        for (int q = 0; q < 4; q++) {
            int e = gate*512 + (nt*8 + 2*tg + (q&1))*16 + g + ((q>>1)<<3);
            base[(e>>4)*17 + (e&15)] += acc[gate][nt][q];
        }
    }
    __syncthreads();
    int tid = threadIdx.x;
#pragma unroll
    for (int i = 0; i < 6; i++) {
        int e = tid + i * 256;
        int ph = (e >> 4) * 17 + (e & 15);
        s_out[e] = s_red[ph] + s_red[1632 + ph] + s_red[3264 + ph] + s_red[4896 + ph];
    }
    __syncthreads();
}

__device__ __forceinline__ float sigf(float x) { return 1.f / (1.f + expf(-x)); }

// ---------------- persistent encoder ----------------
__global__ void __launch_bounds__(256) k_enc(
    const float* __restrict__ bhh0, const float* __restrict__ bih1,
    const float* __restrict__ bhh1)
{
    __shared__ float s_red[4*1632];
    __shared__ float s_gi[1536];
    __shared__ float s_gh[1536];
    int tid = threadIdx.x, lane = tid & 31, warp = tid >> 5;
    int nb = blockIdx.x;
    int jt0 = nb * 16;
    unsigned target = 0;

    {   // zero initial state (64 blocks * 512 = B_*H_)
        int i0 = nb * 512 + tid;
        g_h0P[0][i0] = 0.f; g_h1P[0][i0] = 0.f; g_h0n[0][i0] = 0.f; g_h1n[0][i0] = 0.f;
        int i1 = i0 + 256;
        g_h0P[0][i1] = 0.f; g_h1P[0][i1] = 0.f; g_h0n[0][i1] = 0.f; g_h1n[0][i1] = 0.f;
    }
    gbar(target);

    for (int t = 0; t < S_; t++) {
        int p = t & 1;
        {   // phase A: layer0 gh = whh0 @ h0[p]
            float acc[3][4][4] = {};
            gemvp(acc, g_h0P[p], &g_wp[0][(size_t)nb * WPBLK], lane, warp);
            reduce3(acc, s_red, s_gh);
            for (int v = tid; v < 512; v += 256) {
                int j = v & 15, b = v >> 4;
                int jg = jt0 + j;
                const float* gi = g_gi0 + ((size_t)b * S_ + t) * H3_;
                float r = sigf(gi[jg]        + s_gh[        b*16 + j] + bhh0[jg]);
                float z = sigf(gi[H_ + jg]   + s_gh[ 512 +  b*16 + j] + bhh0[H_ + jg]);
                float ghn =                    s_gh[1024 +  b*16 + j] + bhh0[2*H_ + jg];
                float n = tanhf(gi[2*H_ + jg] + r * ghn);
                float hp = __ldcg(&g_h0n[p][b*H_ + jg]);
                float h = (1.f - z) * n + z * hp;
                g_h0n[1-p][b*H_ + jg] = h;
                g_h0P[1-p][pidx(jg, b)] = roundtf(h);
            }
        }
        gbar(target);
        {   // phase B: layer1 gi = wih1 @ h0[1-p], gh = whh1 @ h1[p]
            float acc[3][4][4] = {};
            gemvp(acc, g_h0P[1-p], &g_wp[1][(size_t)nb * WPBLK], lane, warp);
            reduce3(acc, s_red, s_gi);
            float acc2[3][4][4] = {};
            gemvp(acc2, g_h1P[p], &g_wp[2][(size_t)nb * WPBLK], lane, warp);
            reduce3(acc2, s_red, s_gh);
            for (int v = tid; v < 512; v += 256) {
                int j = v & 15, b = v >> 4;
                int jg = jt0 + j;
                float r = sigf(s_gi[        b*16 + j] + bih1[jg]
                             + s_gh[        b*16 + j] + bhh1[jg]);
                float z = sigf(s_gi[ 512 +  b*16 + j] + bih1[H_ + jg]
                             + s_gh[ 512 +  b*16 + j] + bhh1[H_ + jg]);
                float ghn =    s_gh[1024 +  b*16 + j] + bhh1[2*H_ + jg];
                float gin =    s_gi[1024 +  b*16 + j] + bih1[2*H_ + jg];
                float n = tanhf(gin + r * ghn);
                float hp = __ldcg(&g_h1n[p][b*H_ + jg]);
                float h = (1.f - z) * n + z * hp;
                g_h1n[1-p][b*H_ + jg] = h;
                g_h1P[1-p][pidx(jg, b)] = roundtf(h);
                g_enc[((size_t)b * S_ + t) * H_ + jg] = h;
            }
        }
        gbar(target);
    }
}

// ---------------- persistent decoder ----------------
__global__ void __launch_bounds__(256) k_dec(
    const int* __restrict__ src_ids,
    const float* __restrict__ bhh0, const float* __restrict__ bih1,
    const float* __restrict__ bhh1)
{
    __shared__ float s_red[4*1632];
    __shared__ float s_gi[1536];
    __shared__ float s_gh[1536];
    __shared__ float s_ev[S_];
    __shared__ float s_mxv[2];
    int tid = threadIdx.x, lane = tid & 31, warp = tid >> 5;
    int nb = blockIdx.x;
    int jt0 = nb * 16;
    unsigned target = 0;

    for (int t = 0; t < TD; t++) {
        int p = t & 1;
        {   // P1: attention scores (4 dots per warp)
            int gw = nb * 8 + warp;
#pragma unroll
            for (int dd = 0; dd < 4; dd++) {
                int d = gw * 4 + dd;
                int b = d >> 6, s = d & 63;
                const float* pr = g_proj + ((size_t)b * S_ + s) * H_;
                const float* hv = g_h1n[p] + b * H_;
                float acc = 0.f;
#pragma unroll 8
                for (int k = lane; k < H_; k += 32)
                    acc += __ldg(pr + k) * __ldcg(hv + k);
#pragma unroll
                for (int o = 16; o; o >>= 1) acc += __shfl_xor_sync(0xffffffffu, acc, o);
                if (lane == 0)
                    g_score[d] = (src_ids[b*S_ + s] != 0) ? acc : -1e9f;
            }
        }
        gbar(target);
        {   // P2: softmax + ctx; block -> (batch nb>>1, h-half nb&1)
            int b = nb >> 1;
            if (tid < S_) s_ev[tid] = __ldcg(&g_score[b*S_ + tid]);
            __syncthreads();
            if (tid == 0) {
                float mx = -1e30f;
#pragma unroll
                for (int s = 0; s < S_; s++) mx = fmaxf(mx, s_ev[s]);
                s_mxv[0] = mx;
            }
            __syncthreads();
            if (tid < S_) s_ev[tid] = expf(s_ev[tid] - s_mxv[0]);
            __syncthreads();
            if (tid == 0) {
                float su = 0.f;
#pragma unroll
                for (int s = 0; s < S_; s++) su += s_ev[s];
                s_mxv[1] = 1.f / su;
            }
            __syncthreads();
            float inv = s_mxv[1];
            int hbase = (nb & 1) * 512;
#pragma unroll
            for (int i = 0; i < 2; i++) {
                int h = hbase + tid + i * 256;
                const float* ep = g_enc + (size_t)b * S_ * H_ + h;
                float a = 0.f;
#pragma unroll 8
                for (int s = 0; s < S_; s++) a += s_ev[s] * __ldg(ep + (size_t)s * H_);
                a *= inv;
                float ar = roundtf(a);
                g_xP[pidx(h, b)] = ar;
                g_cat[((size_t)t * B_ + b) * (2*H_) + H_ + h] = ar;
            }
        }
        gbar(target);
        {   // P3: layer0 gi = wih0c @ ctx (+giemb), gh = whh0 @ d0[p]
            float acc[3][4][4] = {};
            gemvp(acc, g_xP, &g_wp[4][(size_t)nb * WPBLK], lane, warp);
            reduce3(acc, s_red, s_gi);
            float acc2[3][4][4] = {};
            gemvp(acc2, g_h0P[p], &g_wp[3][(size_t)nb * WPBLK], lane, warp);
            reduce3(acc2, s_red, s_gh);
            for (int v = tid; v < 512; v += 256) {
                int j = v & 15, b = v >> 4;
                int jg = jt0 + j;
                const float* ge = g_giemb + ((size_t)t * B_ + b) * H3_;
                float r = sigf(s_gi[        b*16 + j] + ge[jg]
                             + s_gh[        b*16 + j] + bhh0[jg]);
                float z = sigf(s_gi[ 512 +  b*16 + j] + ge[H_ + jg]
                             + s_gh[ 512 +  b*16 + j] + bhh0[H_ + jg]);
                float ghn =    s_gh[1024 +  b*16 + j] + bhh0[2*H_ + jg];
                float gin =    s_gi[1024 +  b*16 + j] + ge[2*H_ + jg];
                float n = tanhf(gin + r * ghn);
                float hp = __ldcg(&g_h0n[p][b*H_ + jg]);
                float h = (1.f - z) * n + z * hp;
                g_h0n[1-p][b*H_ + jg] = h;
                g_h0P[1-p][pidx(jg, b)] = roundtf(h);
            }
        }
        gbar(target);
        {   // P4: layer1
            float acc[3][4][4] = {};
            gemvp(acc, g_h0P[1-p], &g_wp[5][(size_t)nb * WPBLK], lane, warp);
            reduce3(acc, s_red, s_gi);
            float acc2[3][4][4] = {};
            gemvp(acc2, g_h1P[p], &g_wp[6][(size_t)nb * WPBLK], lane, warp);
            reduce3(acc2, s_red, s_gh);
            for (int v = tid; v < 512; v += 256) {
                int j = v & 15, b = v >> 4;
                int jg = jt0 + j;
                float r = sigf(s_gi[        b*16 + j] + bih1[jg]
                             + s_gh[        b*16 + j] + bhh1[jg]);
                float z = sigf(s_gi[ 512 +  b*16 + j] + bih1[H_ + jg]
                             + s_gh[ 512 +  b*16 + j] + bhh1[H_ + jg]);
                float ghn =    s_gh[1024 +  b*16 + j] + bhh1[2*H_ + jg];
                float gin =    s_gi[1024 +  b*16 + j] + bih1[2*H_ + jg];
                float n = tanhf(gin + r * ghn);
                float hp = __ldcg(&g_h1n[p][b*H_ + jg]);
                float h = (1.f - z) * n + z * hp;
                g_h1n[1-p][b*H_ + jg] = h;
                g_h1P[1-p][pidx(jg, b)] = roundtf(h);
                g_cat[((size_t)t * B_ + b) * (2*H_) + jg] = roundtf(h);
            }
        }
        gbar(target);
    }
}

// ---------------- tf32 tensor-core GEMM (mode 0: normal, 1: scatter out) ----------------
template<bool CVT>
__global__ __launch_bounds__(256, 2)
void k_gemm_tc(const float* __restrict__ A, int lda,
               const float* __restrict__ W, int ldw,
               const float* __restrict__ bias, float* __restrict__ C,
               int M, int N, int K, int mode)
{
    __shared__ float As[2][128*20];
    __shared__ float Bs[2][128*20];
    const int tid = threadIdx.x;
    const int m0 = blockIdx.x * 128;
    const int n0 = blockIdx.y * 128;
    const int warp = tid >> 5, lane = tid & 31;
    const int g = lane >> 2, tg = lane & 3;
    const int wm = (warp >> 2) * 64, wn = (warp & 3) * 32;

    const int lrow = tid >> 2;
    const int lk   = (tid & 3) * 4;
    int ar0 = m0 + lrow;      if (ar0 >= M) ar0 = M - 1;
    int ar1 = m0 + lrow + 64; if (ar1 >= M) ar1 = M - 1;
    const float* ag0 = A + (size_t)ar0 * lda + lk;
    const float* ag1 = A + (size_t)ar1 * lda + lk;
    const float* bg0 = W + (size_t)(n0 + lrow) * ldw + lk;
    const float* bg1 = W + (size_t)(n0 + lrow + 64) * ldw + lk;
    uint32_t sa0 = (uint32_t)__cvta_generic_to_shared(&As[0][lrow*20 + lk]);
    uint32_t sa1 = (uint32_t)__cvta_generic_to_shared(&As[0][(lrow+64)*20 + lk]);
    uint32_t sb0 = (uint32_t)__cvta_generic_to_shared(&Bs[0][lrow*20 + lk]);
    uint32_t sb1 = (uint32_t)__cvta_generic_to_shared(&Bs[0][(lrow+64)*20 + lk]);
    const uint32_t ssz = 128*20*4;

    float acc[4][4][4];
#pragma unroll
    for (int i = 0; i < 4; i++)
#pragma unroll
        for (int j = 0; j < 4; j++)
#pragma unroll
            for (int q = 0; q < 4; q++) acc[i][j][q] = 0.f;

    auto cv = [](float f) -> uint32_t {
        if (CVT) { uint32_t u; asm("cvt.rna.tf32.f32 %0, %1;" : "=r"(u) : "f"(f)); return u; }
        return __float_as_uint(f);
    };
    auto issue = [&](int st, int c) {
        uint32_t so = st ? ssz : 0;
        const float* p0 = ag0 + c*16;
        const float* p1 = ag1 + c*16;
        const float* p2 = bg0 + c*16;
        const float* p3 = bg1 + c*16;
        asm volatile("cp.async.cg.shared.global [%0], [%1], 16;\n" :: "r"(sa0+so), "l"(p0));
        asm volatile("cp.async.cg.shared.global [%0], [%1], 16;\n" :: "r"(sa1+so), "l"(p1));
        asm volatile("cp.async.cg.shared.global [%0], [%1], 16;\n" :: "r"(sb0+so), "l"(p2));
        asm volatile("cp.async.cg.shared.global [%0], [%1], 16;\n" :: "r"(sb1+so), "l"(p3));
    };

    const int nchunk = K / 16;
    issue(0, 0);
    asm volatile("cp.async.commit_group;\n");

    for (int c = 0; c < nchunk; c++) {
        if (c + 1 < nchunk) issue((c + 1) & 1, c + 1);
        asm volatile("cp.async.commit_group;\n");
        asm volatile("cp.async.wait_group 1;\n");
        __syncthreads();
        const float* as = As[c & 1];
        const float* bs = Bs[c & 1];
#pragma unroll
        for (int ks = 0; ks < 16; ks += 8) {
            uint32_t af[4][4], bf[4][2];
#pragma unroll
            for (int i = 0; i < 4; i++) {
                int r = wm + i*16 + g;
                af[i][0] = cv(as[r*20 + ks + tg]);
                af[i][1] = cv(as[(r+8)*20 + ks + tg]);
                af[i][2] = cv(as[r*20 + ks + tg + 4]);
                af[i][3] = cv(as[(r+8)*20 + ks + tg + 4]);
            }
#pragma unroll
            for (int j = 0; j < 4; j++) {
                int cc = wn + j*8 + g;
                bf[j][0] = cv(bs[cc*20 + ks + tg]);
                bf[j][1] = cv(bs[cc*20 + ks + tg + 4]);
            }
#pragma unroll
            for (int i = 0; i < 4; i++)
#pragma unroll
                for (int j = 0; j < 4; j++)
                    mma_tf32(acc[i][j], af[i], bf[j]);
        }
        __syncthreads();
    }

#pragma unroll
    for (int i = 0; i < 4; i++) {
#pragma unroll
        for (int j = 0; j < 4; j++) {
            int n = n0 + wn + j*8 + 2*tg;
            float bv0 = bias ? bias[n] : 0.f;
            float bv1 = bias ? bias[n + 1] : 0.f;
            int m = m0 + wm + i*16 + g;
            if (m < M) {
                float* o;
                if (mode == 0) o = C + (size_t)m * N + n;
                else { int bb = m & 31, tt = m >> 5; o = C + (size_t)bb*TD*V_ + (size_t)tt*V_ + n; }
                o[0] = acc[i][j][0] + bv0;
                o[1] = acc[i][j][1] + bv1;
            }
            int m2 = m + 8;
            if (m2 < M) {
                float* o;
                if (mode == 0) o = C + (size_t)m2 * N + n;
                else { int bb = m2 & 31, tt = m2 >> 5; o = C + (size_t)bb*TD*V_ + (size_t)tt*V_ + n; }
                o[0] = acc[i][j][2] + bv0;
                o[1] = acc[i][j][3] + bv1;
            }
        }
    }
}

// ---------------- host ----------------
extern "C" void kernel_launch(void* const* d_in, const int* in_sizes, int n_in,
                              void* d_out, int out_size)
{
    const int*   src_ids  = (const int*)d_in[0];
    const int*   tgt_ids  = (const int*)d_in[2];
    const float* enc_emb  = (const float*)d_in[3];
    const float* dec_emb  = (const float*)d_in[4];
    const float* enc_wih0 = (const float*)d_in[5];
    const float* enc_whh0 = (const float*)d_in[6];
    const float* enc_bih0 = (const float*)d_in[7];
    const float* enc_bhh0 = (const float*)d_in[8];
    const float* enc_wih1 = (const float*)d_in[9];
    const float* enc_whh1 = (const float*)d_in[10];
    const float* enc_bih1 = (const float*)d_in[11];
    const float* enc_bhh1 = (const float*)d_in[12];
    const float* dec_wih0 = (const float*)d_in[13];
    const float* dec_whh0 = (const float*)d_in[14];
    const float* dec_bih0 = (const float*)d_in[15];
    const float* dec_bhh0 = (const float*)d_in[16];
    const float* dec_wih1 = (const float*)d_in[17];
    const float* dec_whh1 = (const float*)d_in[18];
    const float* dec_bih1 = (const float*)d_in[19];
    const float* dec_bhh1 = (const float*)d_in[20];
    const float* attn_w   = (const float*)d_in[21];
    const float* out_w    = (const float*)d_in[22];
    const float* out_b    = (const float*)d_in[23];
    float* out = (float*)d_out;

    float *emb, *demb, *gi0, *giemb, *enc, *proj, *cat, *owr, *w0er, *w0dr, *wp;
    cudaGetSymbolAddress((void**)&emb,   g_emb);
    cudaGetSymbolAddress((void**)&demb,  g_demb);
    cudaGetSymbolAddress((void**)&gi0,   g_gi0);
    cudaGetSymbolAddress((void**)&giemb, g_giemb);
    cudaGetSymbolAddress((void**)&enc,   g_enc);
    cudaGetSymbolAddress((void**)&proj,  g_proj);
    cudaGetSymbolAddress((void**)&cat,   g_cat);
    cudaGetSymbolAddress((void**)&owr,   g_owr);
    cudaGetSymbolAddress((void**)&w0er,  g_wih0er);
    cudaGetSymbolAddress((void**)&w0dr,  g_wih0dr);
    cudaGetSymbolAddress((void**)&wp,    g_wp);

    const int wgrid = WPSZ / 256;
    // rounded weight copies + packed recurrent weights
    k_round<<<(H3_*E_ + 255)/256, 256>>>(enc_wih0, w0er, H3_*E_);
    k_round<<<(H3_*(E_+H_) + 255)/256, 256>>>(dec_wih0, w0dr, H3_*(E_+H_));
    k_round<<<(V_*2*H_ + 255)/256, 256>>>(out_w, owr, V_*2*H_);
    k_wpack<<<wgrid, 256>>>(enc_whh0, H_,    0,  wp + 0*(size_t)WPSZ);
    k_wpack<<<wgrid, 256>>>(enc_wih1, H_,    0,  wp + 1*(size_t)WPSZ);
    k_wpack<<<wgrid, 256>>>(enc_whh1, H_,    0,  wp + 2*(size_t)WPSZ);
    k_wpack<<<wgrid, 256>>>(dec_whh0, H_,    0,  wp + 3*(size_t)WPSZ);
    k_wpack<<<wgrid, 256>>>(dec_wih0, E_+H_, E_, wp + 4*(size_t)WPSZ);
    k_wpack<<<wgrid, 256>>>(dec_wih1, H_,    0,  wp + 5*(size_t)WPSZ);
    k_wpack<<<wgrid, 256>>>(dec_whh1, H_,    0,  wp + 6*(size_t)WPSZ);
    // embedding gathers (pre-rounded)
    k_init<<<(B_*S_*E_ + 255)/256, 256>>>(src_ids, enc_emb);
    k_demb<<<(TD*B_*E_ + 255)/256, 256>>>(tgt_ids, dec_emb);

    // batched input-gate GEMMs (no in-loop cvt)
    k_gemm_tc<false><<<dim3((B_*S_)/128, H3_/128), 256>>>(
        emb, E_, w0er, E_, enc_bih0, gi0, B_*S_, H3_, E_, 0);
    k_gemm_tc<false><<<dim3((TD*B_ + 127)/128, H3_/128), 256>>>(
        demb, E_, w0dr, E_+H_, dec_bih0, giemb, TD*B_, H3_, E_, 0);

    // persistent encoder
    k_reset<<<1, 1>>>();
    k_enc<<<NBLK, 256>>>(enc_bhh0, enc_bih1, enc_bhh1);

    // attention projection (enc is full precision -> keep cvt)
    k_gemm_tc<true><<<dim3((B_*S_)/128, H_/128), 256>>>(
        enc, H_, attn_w, H_, nullptr, proj, B_*S_, H_, H_, 0);

    // persistent decoder
    k_reset<<<1, 1>>>();
    k_dec<<<NBLK, 256>>>(src_ids, dec_bhh0, dec_bih1, dec_bhh1);

    // output projection (rounded operands, scatter to (B,TD,V))
    k_gemm_tc<false><<<dim3((TD*B_ + 127)/128, V_/128), 256>>>(
        cat, 2*H_, owr, 2*H_, out_b, out, TD*B_, V_, 2*H_, 1);
}